// round 9
// baseline (speedup 1.0000x reference)
#include <cuda_runtime.h>
#include <cstdint>

#define NBINS     4096        // top-12 bits of the monotone key
#define BIN_SHIFT 20
#define SUB_SHIFT 8           // next 12 bits for tie-bin refinement
#define CAND_MAX  4096
#define NT        1024
#define NGROUPS   64          // 4096 / 64
#define GRP       64
#define PERT      (CAND_MAX / NT)   // 4 candidates per thread max

// Monotone transform: u(a) > u(b)  <=>  a > b  (finite floats)
__device__ __forceinline__ uint32_t key_of(float v) {
    uint32_t b = __float_as_uint(v);
    return (b & 0x80000000u) ? ~b : (b | 0x80000000u);
}

__global__ __launch_bounds__(NT, 1)
void topk_kernel(const float* __restrict__ scores,
                 const int*   __restrict__ bndA,
                 const int*   __restrict__ bndB,
                 float*       __restrict__ out,   // OUTPUT DTYPE = float32
                 int S, int K) {
    __shared__ union {
        uint32_t           hist[NBINS];     // 16 KB
        unsigned long long cand[CAND_MAX];  // 32 KB (union = 32 KB)
    } sh;
    __shared__ uint32_t gsum[NGROUPS];
    __shared__ int s_b, s_n, s_above, s_sub;

    const int row = blockIdx.x;
    const int tid = threadIdx.x;

    const int a = bndA[row], b = bndB[row];
    int start = max(0, min(min(a, b), S));
    int end   = max(start, min(max(a, b), S));
    const float* rowp = scores + (size_t)row * S;
    float* orow = out + (size_t)row * K;

    // Deterministic prefill — every slot written even on degenerate windows.
    for (int k = tid; k < K; k += NT) orow[k] = (float)k;
    if (end - start <= 0) return;

    // ---- zero histogram ----
    for (int i = tid; i < NBINS; i += NT) sh.hist[i] = 0;
    __syncthreads();

    // float4-aligned interior
    int vstart = (start + 3) & ~3; if (vstart > end) vstart = end;
    int vend   = end & ~3;         if (vend < vstart) vend = vstart;
    const float4* vp = reinterpret_cast<const float4*>(rowp);
    const int vlo = vstart >> 2, vhi = vend >> 2;

    // ---- pass 1: histogram of top-12 key bits over [start, end) ----
    for (int i = start + tid; i < vstart; i += NT)
        atomicAdd(&sh.hist[key_of(rowp[i]) >> BIN_SHIFT], 1u);
    for (int i = vend + tid; i < end; i += NT)
        atomicAdd(&sh.hist[key_of(rowp[i]) >> BIN_SHIFT], 1u);
    for (int i = vlo + tid; i < vhi; i += NT) {
        float4 v = vp[i];
        atomicAdd(&sh.hist[key_of(v.x) >> BIN_SHIFT], 1u);
        atomicAdd(&sh.hist[key_of(v.y) >> BIN_SHIFT], 1u);
        atomicAdd(&sh.hist[key_of(v.z) >> BIN_SHIFT], 1u);
        atomicAdd(&sh.hist[key_of(v.w) >> BIN_SHIFT], 1u);
    }
    __syncthreads();

    // ---- group sums ----
    {
        int warp = tid >> 5, lane = tid & 31;
        for (int g = warp; g < NGROUPS; g += NT / 32) {
            uint32_t s = 0;
            #pragma unroll
            for (int j = 0; j < GRP / 32; ++j)
                s += sh.hist[g * GRP + j * 32 + lane];
            #pragma unroll
            for (int o = 16; o > 0; o >>= 1)
                s += __shfl_down_sync(0xffffffffu, s, o);
            if (lane == 0) gsum[g] = s;
        }
    }
    __syncthreads();

    // ---- suffix scan from top: threshold bin + count strictly above ----
    if (tid == 0) {
        uint32_t acc = 0;
        int g = NGROUPS - 1;
        for (; g > 0; --g) {
            if (acc + gsum[g] >= (uint32_t)K) break;
            acc += gsum[g];
        }
        int bb = g * GRP;
        for (int i = GRP - 1; i >= 0; --i) {
            int bin = g * GRP + i;
            if (acc + sh.hist[bin] >= (uint32_t)K) { bb = bin; break; }
            acc += sh.hist[bin];
        }
        s_b = bb;
        s_above = (int)acc;
        s_n = 0;
    }
    __syncthreads();
    const uint32_t bthr = (uint32_t)s_b;
    const int above = s_above;

    // ---- pass 2: gather candidates (bin >= bthr) ----
    // key = (u<<32) | ~idx : value desc, index asc (jax tie-break). Unique keys.
    for (int i = start + tid; i < vstart; i += NT) {
        uint32_t u = key_of(rowp[i]);
        if ((u >> BIN_SHIFT) >= bthr) {
            int p = atomicAdd(&s_n, 1);
            if (p < CAND_MAX)
                sh.cand[p] = ((unsigned long long)u << 32) | (uint32_t)(~i);
        }
    }
    for (int i = vend + tid; i < end; i += NT) {
        uint32_t u = key_of(rowp[i]);
        if ((u >> BIN_SHIFT) >= bthr) {
            int p = atomicAdd(&s_n, 1);
            if (p < CAND_MAX)
                sh.cand[p] = ((unsigned long long)u << 32) | (uint32_t)(~i);
        }
    }
    for (int i = vlo + tid; i < vhi; i += NT) {
        float4 v = vp[i];
        int base = i << 2;
        uint32_t u0 = key_of(v.x), u1 = key_of(v.y), u2 = key_of(v.z), u3 = key_of(v.w);
        if ((u0 >> BIN_SHIFT) >= bthr) {
            int p = atomicAdd(&s_n, 1);
            if (p < CAND_MAX) sh.cand[p] = ((unsigned long long)u0 << 32) | (uint32_t)(~(base + 0));
        }
        if ((u1 >> BIN_SHIFT) >= bthr) {
            int p = atomicAdd(&s_n, 1);
            if (p < CAND_MAX) sh.cand[p] = ((unsigned long long)u1 << 32) | (uint32_t)(~(base + 1));
        }
        if ((u2 >> BIN_SHIFT) >= bthr) {
            int p = atomicAdd(&s_n, 1);
            if (p < CAND_MAX) sh.cand[p] = ((unsigned long long)u2 << 32) | (uint32_t)(~(base + 2));
        }
        if ((u3 >> BIN_SHIFT) >= bthr) {
            int p = atomicAdd(&s_n, 1);
            if (p < CAND_MAX) sh.cand[p] = ((unsigned long long)u3 << 32) | (uint32_t)(~(base + 3));
        }
    }
    __syncthreads();
    int n = s_n;

    // ---- rare overflow: refine threshold inside the tie bin (exact any shape) ----
    if (n > CAND_MAX) {
        __syncthreads();
        for (int i = tid; i < NBINS; i += NT) sh.hist[i] = 0;
        if (tid == 0) s_n = 0;
        __syncthreads();
        for (int i = start + tid; i < end; i += NT) {
            uint32_t u = key_of(rowp[i]);
            if ((u >> BIN_SHIFT) == bthr)
                atomicAdd(&sh.hist[(u >> SUB_SHIFT) & 0xFFFu], 1u);
        }
        __syncthreads();
        if (tid == 0) {
            uint32_t need = (uint32_t)(K - above);
            uint32_t acc = 0;
            int sb = 0;
            for (int i = NBINS - 1; i >= 0; --i) {
                if (acc + sh.hist[i] >= need) { sb = i; break; }
                acc += sh.hist[i];
            }
            s_sub = sb;
        }
        __syncthreads();
        const uint32_t ssub = (uint32_t)s_sub;
        __syncthreads();   // all threads read s_sub before cand[] aliases hist[]
        for (int i = start + tid; i < end; i += NT) {
            uint32_t u = key_of(rowp[i]);
            uint32_t bin = u >> BIN_SHIFT;
            if (bin > bthr || (bin == bthr && ((u >> SUB_SHIFT) & 0xFFFu) >= ssub)) {
                int p = atomicAdd(&s_n, 1);
                if (p < CAND_MAX)
                    sh.cand[p] = ((unsigned long long)u << 32) | (uint32_t)(~i);
            }
        }
        __syncthreads();
        n = min(s_n, CAND_MAX);
    } else {
        n = min(n, CAND_MAX);
    }

    // ---- exact rank: slot = #candidates with strictly larger key ----
    unsigned long long my[PERT];
    int cnt = 0;
    for (int i = tid; i < n; i += NT) my[cnt++] = sh.cand[i];

    int rank[PERT];
    #pragma unroll
    for (int c = 0; c < PERT; ++c) rank[c] = 0;

    for (int j = 0; j < n; ++j) {
        unsigned long long k = sh.cand[j];   // broadcast smem read — conflict-free
        #pragma unroll
        for (int c = 0; c < PERT; ++c)
            if (c < cnt) rank[c] += (k > my[c]);
    }

    // Write indices AS FLOAT VALUES (output dtype = float32; exact for idx < 2^24).
    #pragma unroll
    for (int c = 0; c < PERT; ++c)
        if (c < cnt && rank[c] < K)
            orow[rank[c]] = (float)(int)(~(uint32_t)my[c]);
}

extern "C" void kernel_launch(void* const* d_in, const int* in_sizes, int n_in,
                              void* d_out, int out_size) {
    // Derive ALL shapes from runtime sizes.
    int big = 0;
    for (int i = 1; i < n_in; ++i)
        if (in_sizes[i] > in_sizes[big]) big = i;
    int s0 = -1, s1 = -1;
    for (int i = 0; i < n_in; ++i) {
        if (i == big) continue;
        if (s0 < 0) s0 = i; else if (s1 < 0) s1 = i;
    }

    const int B = in_sizes[s0];
    const int S = in_sizes[big] / (B > 0 ? B : 1);
    const int K = out_size / (B > 0 ? B : 1);

    const float* scores = (const float*)d_in[big];
    const int*   bA     = (const int*)d_in[s0];
    const int*   bB     = (const int*)d_in[s1];
    float*       out    = (float*)d_out;

    topk_kernel<<<B, NT>>>(scores, bA, bB, out, S, K);
}

// round 10
// speedup vs baseline: 3.8447x; 3.8447x over previous
#include <cuda_runtime.h>
#include <cstdint>

#define NBINS     8192        // raw top-13 bits of float bits
#define BIN_SHIFT 19
#define SUB_SHIFT 7           // next 12 bits for tie-bin refinement
#define CAND_MAX  4096
#define SORT_N    4096
#define NT        1024
#define NGROUPS   128         // 8192 / 64
#define GRP       64

// Monotone transform: u(a) > u(b)  <=>  a > b  (finite floats). Used only for
// the packed sort keys of the ~1-2% of elements that pass the threshold.
__device__ __forceinline__ uint32_t key_of(float v) {
    uint32_t b = __float_as_uint(v);
    return (b & 0x80000000u) ? ~b : (b | 0x80000000u);
}

// Descending-value position -> raw bin index.
// Positives: bins 0x0000..0x0FFF (value ascending with bin)  -> positions 0..4095 from bin 0x0FFF down.
// Negatives: bins 0x1000..0x1FFF (value DEscending with bin) -> positions 4096..8191 from bin 0x1000 up.
__device__ __forceinline__ int bin_of_pos(int p) {
    return (p < 4096) ? (0x0FFF - p) : p;
}

__global__ __launch_bounds__(NT, 1)
void topk_kernel(const float* __restrict__ scores,
                 const int*   __restrict__ bndA,
                 const int*   __restrict__ bndB,
                 float*       __restrict__ out,   // output dtype = float32
                 int S, int K) {
    __shared__ union {
        uint32_t           hist[NBINS];    // 32 KB (pass 1 / refinement)
        unsigned long long cand[SORT_N];   // 32 KB (gather + bitonic sort)
    } sh;
    __shared__ uint32_t gsum[NGROUPS];
    __shared__ float s_thr;
    __shared__ int s_bb, s_refine, s_neg, s_n;

    const int row = blockIdx.x;
    const int tid = threadIdx.x;

    const int a = bndA[row], b = bndB[row];
    int start = max(0, min(min(a, b), S));
    int end   = max(start, min(max(a, b), S));
    const float* rowp = scores + (size_t)row * S;
    float* orow = out + (size_t)row * K;

    if (end - start <= 0) {               // degenerate: deterministic fill
        for (int k = tid; k < K; k += NT) orow[k] = (float)k;
        return;
    }

    // ---- zero histogram ----
    for (int i = tid; i < NBINS; i += NT) sh.hist[i] = 0;
    __syncthreads();

    // float4-aligned interior
    int vstart = (start + 3) & ~3; if (vstart > end) vstart = end;
    int vend   = end & ~3;         if (vend < vstart) vend = vstart;
    const float4* vp = reinterpret_cast<const float4*>(rowp);
    const int vlo = vstart >> 2, vhi = vend >> 2;

    // ---- pass 1: histogram raw top-13 bits (no key transform per element) ----
    for (int i = start + tid; i < vstart; i += NT)
        atomicAdd(&sh.hist[__float_as_uint(rowp[i]) >> BIN_SHIFT], 1u);
    for (int i = vend + tid; i < end; i += NT)
        atomicAdd(&sh.hist[__float_as_uint(rowp[i]) >> BIN_SHIFT], 1u);
    for (int i = vlo + tid; i < vhi; i += NT) {
        float4 v = vp[i];
        atomicAdd(&sh.hist[__float_as_uint(v.x) >> BIN_SHIFT], 1u);
        atomicAdd(&sh.hist[__float_as_uint(v.y) >> BIN_SHIFT], 1u);
        atomicAdd(&sh.hist[__float_as_uint(v.z) >> BIN_SHIFT], 1u);
        atomicAdd(&sh.hist[__float_as_uint(v.w) >> BIN_SHIFT], 1u);
    }
    __syncthreads();

    // ---- group sums over descending-VALUE positions ----
    {
        int warp = tid >> 5, lane = tid & 31;
        for (int g = warp; g < NGROUPS; g += NT / 32) {
            uint32_t s = 0;
            #pragma unroll
            for (int j = 0; j < GRP / 32; ++j)
                s += sh.hist[bin_of_pos(g * GRP + j * 32 + lane)];
            #pragma unroll
            for (int o = 16; o > 0; o >>= 1)
                s += __shfl_down_sync(0xffffffffu, s, o);
            if (lane == 0) gsum[g] = s;
        }
    }
    __syncthreads();

    // ---- thread 0: find tie bin in value order, derive float threshold ----
    if (tid == 0) {
        uint32_t acc = 0;
        int g = 0;
        for (; g < NGROUPS; ++g) {
            if (acc + gsum[g] >= (uint32_t)K) break;
            acc += gsum[g];
        }
        if (g == NGROUPS) {                 // window smaller than K: take all
            s_thr = -3.4e38f;
            s_refine = 0;
            s_bb = -1;
        } else {
            int pp = g * GRP;
            for (int t = 0; t < GRP; ++t) {
                int p = g * GRP + t;
                if (acc + sh.hist[bin_of_pos(p)] >= (uint32_t)K) { pp = p; break; }
                acc += sh.hist[bin_of_pos(p)];
            }
            int bin = bin_of_pos(pp);
            bool neg = (pp >= 4096);
            s_bb = bin;
            s_neg = neg;
            if (acc + sh.hist[bin] <= CAND_MAX) {
                // smallest value in tie bin: pos -> low bits 0; neg -> low bits all 1
                uint32_t tb = ((uint32_t)bin << BIN_SHIFT) | (neg ? 0x7FFFFu : 0u);
                s_thr = __uint_as_float(tb);
                s_refine = 0;
            } else {
                s_refine = 1;               // rare: tie bin too fat, refine below
                s_thr = (float)(int)acc;    // stash 'above' count for refine step
            }
        }
        s_n = 0;
    }
    __syncthreads();

    // ---- rare refinement: 12 more bits inside the tie bin ----
    if (s_refine) {
        const uint32_t bb = (uint32_t)s_bb;
        const int above = (int)s_thr;
        for (int i = tid; i < 4096; i += NT) sh.hist[i] = 0;
        __syncthreads();
        for (int i = start + tid; i < end; i += NT) {
            uint32_t bx = __float_as_uint(rowp[i]);
            if ((bx >> BIN_SHIFT) == bb)
                atomicAdd(&sh.hist[(bx >> SUB_SHIFT) & 0xFFFu], 1u);
        }
        __syncthreads();
        if (tid == 0) {
            uint32_t need = (uint32_t)(K - above);
            uint32_t acc = 0;
            uint32_t tb;
            if (!s_neg) {      // positive: value desc == sub index desc
                int ss = 0;
                for (int i = 4095; i >= 0; --i) {
                    if (acc + sh.hist[i] >= need) { ss = i; break; }
                    acc += sh.hist[i];
                }
                tb = (bb << BIN_SHIFT) | ((uint32_t)ss << SUB_SHIFT);
            } else {           // negative: value desc == sub index asc
                int ss = 4095;
                for (int i = 0; i < 4096; ++i) {
                    if (acc + sh.hist[i] >= need) { ss = i; break; }
                    acc += sh.hist[i];
                }
                tb = (bb << BIN_SHIFT) | ((uint32_t)ss << SUB_SHIFT) | 0x7Fu;
            }
            s_thr = __uint_as_float(tb);
        }
        __syncthreads();
    }

    const float thr = s_thr;

    // ---- zero candidate buffer (pad = 0 sorts last) ----
    __syncthreads();   // everyone done with hist before aliasing as cand
    for (int i = tid; i < SORT_N; i += NT) sh.cand[i] = 0ull;
    __syncthreads();

    // ---- pass 2: gather candidates with one float compare per element ----
    // key = (u<<32) | ~idx : value desc, index asc (jax tie-break). Unique keys.
    for (int i = start + tid; i < vstart; i += NT) {
        float v = rowp[i];
        if (v >= thr) {
            int p = atomicAdd(&s_n, 1);
            if (p < CAND_MAX)
                sh.cand[p] = ((unsigned long long)key_of(v) << 32) | (uint32_t)(~i);
        }
    }
    for (int i = vend + tid; i < end; i += NT) {
        float v = rowp[i];
        if (v >= thr) {
            int p = atomicAdd(&s_n, 1);
            if (p < CAND_MAX)
                sh.cand[p] = ((unsigned long long)key_of(v) << 32) | (uint32_t)(~i);
        }
    }
    for (int i = vlo + tid; i < vhi; i += NT) {
        float4 v = vp[i];
        int base = i << 2;
        if (v.x >= thr) {
            int p = atomicAdd(&s_n, 1);
            if (p < CAND_MAX) sh.cand[p] = ((unsigned long long)key_of(v.x) << 32) | (uint32_t)(~(base + 0));
        }
        if (v.y >= thr) {
            int p = atomicAdd(&s_n, 1);
            if (p < CAND_MAX) sh.cand[p] = ((unsigned long long)key_of(v.y) << 32) | (uint32_t)(~(base + 1));
        }
        if (v.z >= thr) {
            int p = atomicAdd(&s_n, 1);
            if (p < CAND_MAX) sh.cand[p] = ((unsigned long long)key_of(v.z) << 32) | (uint32_t)(~(base + 2));
        }
        if (v.w >= thr) {
            int p = atomicAdd(&s_n, 1);
            if (p < CAND_MAX) sh.cand[p] = ((unsigned long long)key_of(v.w) << 32) | (uint32_t)(~(base + 3));
        }
    }
    __syncthreads();
    const int n = min(s_n, CAND_MAX);

    // ---- bitonic sort 4096 u64, descending ----
    for (int kk = 2; kk <= SORT_N; kk <<= 1) {
        for (int j = kk >> 1; j > 0; j >>= 1) {
            #pragma unroll
            for (int m = 0; m < SORT_N / NT; ++m) {
                int i = tid + m * NT;
                int ixj = i ^ j;
                if (ixj > i) {
                    unsigned long long x = sh.cand[i], y = sh.cand[ixj];
                    bool up = ((i & kk) == 0);
                    if (up ? (x < y) : (x > y)) {
                        sh.cand[i] = y;
                        sh.cand[ixj] = x;
                    }
                }
            }
            __syncthreads();
        }
    }

    // ---- emit: top-K indices, as float values ----
    for (int k = tid; k < K; k += NT)
        orow[k] = (k < n) ? (float)(int)(~(uint32_t)sh.cand[k]) : (float)k;
}

extern "C" void kernel_launch(void* const* d_in, const int* in_sizes, int n_in,
                              void* d_out, int out_size) {
    // Derive all shapes from runtime sizes.
    int big = 0;
    for (int i = 1; i < n_in; ++i)
        if (in_sizes[i] > in_sizes[big]) big = i;
    int s0 = -1, s1 = -1;
    for (int i = 0; i < n_in; ++i) {
        if (i == big) continue;
        if (s0 < 0) s0 = i; else if (s1 < 0) s1 = i;
    }

    const int B = in_sizes[s0];
    const int S = in_sizes[big] / (B > 0 ? B : 1);
    const int K = out_size / (B > 0 ? B : 1);

    const float* scores = (const float*)d_in[big];
    const int*   bA     = (const int*)d_in[s0];
    const int*   bB     = (const int*)d_in[s1];
    float*       outp   = (float*)d_out;

    topk_kernel<<<B, NT>>>(scores, bA, bB, outp, S, K);
}